// round 5
// baseline (speedup 1.0000x reference)
#include <cuda_runtime.h>
#include <cuda_bf16.h>

#define FULL 0xffffffffu
#define R4 0.70710678118654752440f

struct C2 { float x, y; };
__device__ __forceinline__ C2 mkc(float x, float y){ C2 c; c.x=x; c.y=y; return c; }
__device__ __forceinline__ C2 cmul(C2 a, C2 b){
    return mkc(fmaf(a.x,b.x,-a.y*b.y), fmaf(a.x,b.y,a.y*b.x));
}
// a*b + c
__device__ __forceinline__ C2 cmadd(C2 a, C2 b, C2 c){
    return mkc(fmaf(a.x,b.x,fmaf(-a.y,b.y,c.x)), fmaf(a.x,b.y,fmaf(a.y,b.x,c.y)));
}

// Qubit q lives at bit position p = 7-q of amplitude index (lane*8 + k).
// p in {0,1,2}: thread-local register bit.  p in {3..7}: lane bit (p-3).

// ---------------- generic complex 1q gate ----------------
template<int Q>
__device__ __forceinline__ void g1(C2 a[8], C2 u00, C2 u01, C2 u10, C2 u11, int lane){
    constexpr int p = 7 - Q;
    if constexpr (p < 3) {
        constexpr int m = 1 << p;
        #pragma unroll
        for (int k0 = 0; k0 < 8; ++k0) {
            if ((k0 & m) == 0) {
                int k1 = k0 | m;
                C2 a0 = a[k0], a1 = a[k1];
                a[k0] = cmadd(u01, a1, cmul(u00, a0));
                a[k1] = cmadd(u11, a1, cmul(u10, a0));
            }
        }
    } else {
        constexpr int m = 1 << (p - 3);
        bool hi = (lane & m) != 0;
        C2 cA = hi ? u11 : u00;
        C2 cB = hi ? u10 : u01;
        #pragma unroll
        for (int k = 0; k < 8; ++k) {
            C2 part;
            part.x = __shfl_xor_sync(FULL, a[k].x, m);
            part.y = __shfl_xor_sync(FULL, a[k].y, m);
            a[k] = cmadd(cB, part, cmul(cA, a[k]));
        }
    }
}

// ---------------- RY (real 2x2) ----------------
template<int Q>
__device__ __forceinline__ void gry(C2 a[8], float c, float s, int lane){
    constexpr int p = 7 - Q;
    if constexpr (p < 3) {
        constexpr int m = 1 << p;
        #pragma unroll
        for (int k0 = 0; k0 < 8; ++k0) if (!(k0 & m)) {
            int k1 = k0 | m;
            C2 a0 = a[k0], a1 = a[k1];
            a[k0].x = fmaf(c, a0.x, -s*a1.x); a[k0].y = fmaf(c, a0.y, -s*a1.y);
            a[k1].x = fmaf(s, a0.x,  c*a1.x); a[k1].y = fmaf(s, a0.y,  c*a1.y);
        }
    } else {
        constexpr int m = 1 << (p - 3);
        float sg = (lane & m) ? s : -s;
        #pragma unroll
        for (int k = 0; k < 8; ++k) {
            float px = __shfl_xor_sync(FULL, a[k].x, m);
            float py = __shfl_xor_sync(FULL, a[k].y, m);
            a[k].x = fmaf(c, a[k].x, sg*px);
            a[k].y = fmaf(c, a[k].y, sg*py);
        }
    }
}

// ---------------- RZ (diagonal: w0 for bit=0, w1 for bit=1) ----------------
template<int Q>
__device__ __forceinline__ void grz(C2 a[8], C2 w0, C2 w1, int lane){
    constexpr int p = 7 - Q;
    if constexpr (p < 3) {
        constexpr int m = 1 << p;
        #pragma unroll
        for (int k = 0; k < 8; ++k) a[k] = cmul(a[k], (k & m) ? w1 : w0);
    } else {
        constexpr int m = 1 << (p - 3);
        C2 w = (lane & m) ? w1 : w0;
        #pragma unroll
        for (int k = 0; k < 8; ++k) a[k] = cmul(a[k], w);
    }
}

// ---------------- CX (control QC, target QT) ----------------
template<int QC, int QT>
__device__ __forceinline__ void gcx(C2 a[8], int lane){
    constexpr int pc = 7 - QC, pt = 7 - QT;
    if constexpr (pc < 3 && pt < 3) {
        constexpr int mc = 1 << pc, mt = 1 << pt;
        #pragma unroll
        for (int k0 = 0; k0 < 8; ++k0) if ((k0 & mc) && !(k0 & mt)) {
            int k1 = k0 | mt; C2 t = a[k0]; a[k0] = a[k1]; a[k1] = t;
        }
    } else if constexpr (pc < 3) { // control local, target lane
        constexpr int mc = 1 << pc, mt = 1 << (pt - 3);
        #pragma unroll
        for (int k = 0; k < 8; ++k) if (k & mc) {
            a[k].x = __shfl_xor_sync(FULL, a[k].x, mt);
            a[k].y = __shfl_xor_sync(FULL, a[k].y, mt);
        }
    } else if constexpr (pt < 3) { // control lane, target local
        constexpr int mc = 1 << (pc - 3), mt = 1 << pt;
        bool cb = (lane & mc) != 0;
        #pragma unroll
        for (int k0 = 0; k0 < 8; ++k0) if (!(k0 & mt)) {
            int k1 = k0 | mt;
            C2 t0 = a[k0], t1 = a[k1];
            a[k0] = cb ? t1 : t0;
            a[k1] = cb ? t0 : t1;
        }
    } else { // both lane
        constexpr int mc = 1 << (pc - 3), mt = 1 << (pt - 3);
        bool cb = (lane & mc) != 0;
        #pragma unroll
        for (int k = 0; k < 8; ++k) {
            float px = __shfl_xor_sync(FULL, a[k].x, mt);
            float py = __shfl_xor_sync(FULL, a[k].y, mt);
            if (cb) { a[k].x = px; a[k].y = py; }
        }
    }
}

// ---------------- CRX (control QC, target QT); on ctrl=1: RX(t) ----------------
// a0' = c*a0 - i*s*a1 ; a1' = -i*s*a0 + c*a1  (symmetric in target bit)
template<int QC, int QT>
__device__ __forceinline__ void gcrx(C2 a[8], float c, float s, int lane){
    constexpr int pc = 7 - QC, pt = 7 - QT;
    if constexpr (pc < 3 && pt < 3) {
        constexpr int mc = 1 << pc, mt = 1 << pt;
        #pragma unroll
        for (int k0 = 0; k0 < 8; ++k0) if ((k0 & mc) && !(k0 & mt)) {
            int k1 = k0 | mt;
            C2 a0 = a[k0], a1 = a[k1];
            a[k0].x = fmaf(c, a0.x,  s*a1.y); a[k0].y = fmaf(c, a0.y, -s*a1.x);
            a[k1].x = fmaf(c, a1.x,  s*a0.y); a[k1].y = fmaf(c, a1.y, -s*a0.x);
        }
    } else if constexpr (pc < 3) { // control local, target lane
        constexpr int mc = 1 << pc, mt = 1 << (pt - 3);
        #pragma unroll
        for (int k = 0; k < 8; ++k) if (k & mc) {
            float px = __shfl_xor_sync(FULL, a[k].x, mt);
            float py = __shfl_xor_sync(FULL, a[k].y, mt);
            float nx = fmaf(c, a[k].x,  s*py);
            float ny = fmaf(c, a[k].y, -s*px);
            a[k].x = nx; a[k].y = ny;
        }
    } else if constexpr (pt < 3) { // control lane, target local
        constexpr int mc = 1 << (pc - 3), mt = 1 << pt;
        bool cb = (lane & mc) != 0;
        float ce = cb ? c : 1.0f;
        float se = cb ? s : 0.0f;
        #pragma unroll
        for (int k0 = 0; k0 < 8; ++k0) if (!(k0 & mt)) {
            int k1 = k0 | mt;
            C2 a0 = a[k0], a1 = a[k1];
            a[k0].x = fmaf(ce, a0.x,  se*a1.y); a[k0].y = fmaf(ce, a0.y, -se*a1.x);
            a[k1].x = fmaf(ce, a1.x,  se*a0.y); a[k1].y = fmaf(ce, a1.y, -se*a0.x);
        }
    } else { // both lane
        constexpr int mc = 1 << (pc - 3), mt = 1 << (pt - 3);
        bool cb = (lane & mc) != 0;
        float ce = cb ? c : 1.0f;
        float se = cb ? s : 0.0f;
        #pragma unroll
        for (int k = 0; k < 8; ++k) {
            float px = __shfl_xor_sync(FULL, a[k].x, mt);
            float py = __shfl_xor_sync(FULL, a[k].y, mt);
            float nx = fmaf(ce, a[k].x,  se*py);
            float ny = fmaf(ce, a[k].y, -se*px);
            a[k].x = nx; a[k].y = ny;
        }
    }
}

// ---------------- real-state versions for encode (RY + CX only) ----------------
template<int Q>
__device__ __forceinline__ void gryR(float r[8], float c, float s, int lane){
    constexpr int p = 7 - Q;
    if constexpr (p < 3) {
        constexpr int m = 1 << p;
        #pragma unroll
        for (int k0 = 0; k0 < 8; ++k0) if (!(k0 & m)) {
            int k1 = k0 | m;
            float a0 = r[k0], a1 = r[k1];
            r[k0] = fmaf(c, a0, -s*a1);
            r[k1] = fmaf(s, a0,  c*a1);
        }
    } else {
        constexpr int m = 1 << (p - 3);
        float sg = (lane & m) ? s : -s;
        #pragma unroll
        for (int k = 0; k < 8; ++k) {
            float pv = __shfl_xor_sync(FULL, r[k], m);
            r[k] = fmaf(c, r[k], sg*pv);
        }
    }
}

template<int QC, int QT>
__device__ __forceinline__ void gcxR(float r[8], int lane){
    constexpr int pc = 7 - QC, pt = 7 - QT;
    if constexpr (pc < 3 && pt < 3) {
        constexpr int mc = 1 << pc, mt = 1 << pt;
        #pragma unroll
        for (int k0 = 0; k0 < 8; ++k0) if ((k0 & mc) && !(k0 & mt)) {
            int k1 = k0 | mt; float t = r[k0]; r[k0] = r[k1]; r[k1] = t;
        }
    } else if constexpr (pc < 3) {
        constexpr int mc = 1 << pc, mt = 1 << (pt - 3);
        #pragma unroll
        for (int k = 0; k < 8; ++k) if (k & mc)
            r[k] = __shfl_xor_sync(FULL, r[k], mt);
    } else if constexpr (pt < 3) {
        constexpr int mc = 1 << (pc - 3), mt = 1 << pt;
        bool cb = (lane & mc) != 0;
        #pragma unroll
        for (int k0 = 0; k0 < 8; ++k0) if (!(k0 & mt)) {
            int k1 = k0 | mt;
            float t0 = r[k0], t1 = r[k1];
            r[k0] = cb ? t1 : t0;
            r[k1] = cb ? t0 : t1;
        }
    } else {
        constexpr int mc = 1 << (pc - 3), mt = 1 << (pt - 3);
        bool cb = (lane & mc) != 0;
        #pragma unroll
        for (int k = 0; k < 8; ++k) {
            float pv = __shfl_xor_sync(FULL, r[k], mt);
            r[k] = cb ? pv : r[k];
        }
    }
}

__device__ __forceinline__ float wsum(float v){
    #pragma unroll
    for (int o = 16; o; o >>= 1) v += __shfl_xor_sync(FULL, v, o);
    return v;
}

__global__ void __launch_bounds__(256)
qcnn_kernel(const float* __restrict__ x,
            const float* __restrict__ rz_p,  const float* __restrict__ ry_p,
            const float* __restrict__ ry2_p, const float* __restrict__ crx_p,
            const float* __restrict__ u3_p,  const float* __restrict__ u3b_p,
            const float* __restrict__ W1,    const float* __restrict__ b1,
            const float* __restrict__ W2,    const float* __restrict__ b2,
            float* __restrict__ out, int B)
{
    const int gwarp = (blockIdx.x * blockDim.x + threadIdx.x) >> 5;
    const int lane  = threadIdx.x & 31;
    if (gwarp >= B) return;

    // ================= encode (state is purely REAL) =================
    float ang = x[gwarp * 32 + lane];
    float myc, mys;
    __sincosf(0.5f * ang, &mys, &myc);

    float r[8];
    #pragma unroll
    for (int k = 0; k < 8; ++k) r[k] = 0.0f;
    r[0] = (lane == 0) ? 1.0f : 0.0f;

    #define RYQ(CY,Q) gryR<Q>(r, __shfl_sync(FULL, myc, (CY)*8+(Q)), \
                                 __shfl_sync(FULL, mys, (CY)*8+(Q)), lane)
    #define ENC_CYC(CY) \
        RYQ(CY,0); RYQ(CY,1); RYQ(CY,2); RYQ(CY,3); \
        RYQ(CY,4); RYQ(CY,5); RYQ(CY,6); RYQ(CY,7); \
        gcxR<0,1>(r,lane); gcxR<1,2>(r,lane); gcxR<2,3>(r,lane); gcxR<3,4>(r,lane); \
        gcxR<4,5>(r,lane); gcxR<5,6>(r,lane); gcxR<6,7>(r,lane); gcxR<7,0>(r,lane);

    ENC_CYC(0) ENC_CYC(1) ENC_CYC(2) ENC_CYC(3)

    // ================= psi0 parameters =================
    float rc[2], rzs_[2], yc[2], ys[2], y2c[2], y2s[2];
    C2 A00[2], A01[2], A10[2], A11[2];
    #pragma unroll
    for (int l = 0; l < 2; ++l) {
        __sincosf(rz_p[l]  * 0.5f, &rzs_[l], &rc[l]);
        __sincosf(ry_p[l]  * 0.5f, &ys[l],   &yc[l]);
        __sincosf(ry2_p[l] * 0.5f, &y2s[l],  &y2c[l]);
        float t = u3_p[l*3+0], ph = u3_p[l*3+1], la = u3_p[l*3+2];
        float st, ct, sp, cp, sl, cl, spl, cpl;
        __sincosf(t * 0.5f, &st, &ct);
        __sincosf(ph, &sp, &cp);
        __sincosf(la, &sl, &cl);
        __sincosf(ph + la, &spl, &cpl);
        A00[l] = mkc(ct, 0.f);
        A01[l] = mkc(-cl*st, -sl*st);
        A10[l] = mkc( cp*st,  sp*st);
        A11[l] = mkc(cpl*ct, spl*ct);
    }

    // ================= psi0 circuit =================
    C2 a[8];
    #pragma unroll
    for (int k = 0; k < 8; ++k) a[k] = mkc(r[k], 0.f);

    #define BLK(QC,QT,L) \
        grz<QT>(a, mkc(R4, R4),  mkc(R4,-R4), lane); \
        gcx<QT,QC>(a, lane); \
        grz<QC>(a, mkc(rc[L],-rzs_[L]), mkc(rc[L],rzs_[L]), lane); \
        gry<QT>(a, yc[L], ys[L], lane); \
        gcx<QC,QT>(a, lane); \
        gry<QT>(a, y2c[L], y2s[L], lane); \
        gcx<QT,QC>(a, lane); \
        grz<QC>(a, mkc(R4,-R4), mkc(R4, R4), lane);

    BLK(0,1,0) BLK(2,3,0) BLK(4,5,0) BLK(6,7,0)
    BLK(1,2,0) BLK(3,4,0) BLK(5,6,0)
    g1<1>(a, A00[0], A01[0], A10[0], A11[0], lane);
    g1<3>(a, A00[0], A01[0], A10[0], A11[0], lane);
    g1<5>(a, A00[0], A01[0], A10[0], A11[0], lane);
    g1<7>(a, A00[0], A01[0], A10[0], A11[0], lane);
    BLK(1,3,1) BLK(5,7,1) BLK(3,5,1)
    g1<3>(a, A00[1], A01[1], A10[1], A11[1], lane);
    g1<7>(a, A00[1], A01[1], A10[1], A11[1], lane);

    // measure psi0: <Z_3> (lane bit 1), <Z_7> (k bit 0)
    float pn = 0.f, p7 = 0.f;
    #pragma unroll
    for (int k = 0; k < 8; ++k) {
        float m = fmaf(a[k].x, a[k].x, a[k].y * a[k].y);
        pn += m;
        p7 += (k & 1) ? -m : m;
    }
    float sgn3 = ((lane >> 1) & 1) ? -1.f : 1.f;
    float f0 = wsum(sgn3 * pn);
    float f1 = wsum(p7);

    // ================= psi1 parameters =================
    float xcf[2], xsf[2];
    C2 B00[2], B01[2], B10[2], B11[2];
    #pragma unroll
    for (int l = 0; l < 2; ++l) {
        __sincosf(crx_p[l] * 0.5f, &xsf[l], &xcf[l]);
        float t = u3b_p[l*3+0], ph = u3b_p[l*3+1], la = u3b_p[l*3+2];
        float st, ct, sp, cp, sl, cl, spl, cpl;
        __sincosf(t * 0.5f, &st, &ct);
        __sincosf(ph, &sp, &cp);
        __sincosf(la, &sl, &cl);
        __sincosf(ph + la, &spl, &cpl);
        B00[l] = mkc(ct, 0.f);
        B01[l] = mkc(-cl*st, -sl*st);
        B10[l] = mkc( cp*st,  sp*st);
        B11[l] = mkc(cpl*ct, spl*ct);
    }

    // ================= psi1 circuit =================
    #pragma unroll
    for (int k = 0; k < 8; ++k) a[k] = mkc(r[k], 0.f);

    gcrx<0,1>(a, xcf[0], xsf[0], lane);
    gcrx<2,3>(a, xcf[0], xsf[0], lane);
    gcrx<4,5>(a, xcf[0], xsf[0], lane);
    gcrx<6,7>(a, xcf[0], xsf[0], lane);
    gcrx<1,2>(a, xcf[0], xsf[0], lane);
    gcrx<3,4>(a, xcf[0], xsf[0], lane);
    gcrx<5,6>(a, xcf[0], xsf[0], lane);
    g1<1>(a, B00[0], B01[0], B10[0], B11[0], lane);
    g1<3>(a, B00[0], B01[0], B10[0], B11[0], lane);
    g1<5>(a, B00[0], B01[0], B10[0], B11[0], lane);
    g1<7>(a, B00[0], B01[0], B10[0], B11[0], lane);
    gcrx<1,3>(a, xcf[1], xsf[1], lane);
    gcrx<5,7>(a, xcf[1], xsf[1], lane);
    gcrx<3,5>(a, xcf[1], xsf[1], lane);
    g1<3>(a, B00[1], B01[1], B10[1], B11[1], lane);
    g1<7>(a, B00[1], B01[1], B10[1], B11[1], lane);

    // measure psi1
    pn = 0.f; p7 = 0.f;
    #pragma unroll
    for (int k = 0; k < 8; ++k) {
        float m = fmaf(a[k].x, a[k].x, a[k].y * a[k].y);
        pn += m;
        p7 += (k & 1) ? -m : m;
    }
    float f2 = wsum(sgn3 * pn);
    float f3 = wsum(p7);

    // ================= MLP head =================
    float hv = 0.f;
    if (lane < 15) {
        float z = b1[lane];
        z = fmaf(W1[lane*4+0], f0, z);
        z = fmaf(W1[lane*4+1], f1, z);
        z = fmaf(W1[lane*4+2], f2, z);
        z = fmaf(W1[lane*4+3], f3, z);
        hv = tanhf(z) * W2[lane];
    }
    float s = wsum(hv);
    if (lane == 0) {
        float zf = s + b2[0];
        out[gwarp] = 1.0f / (1.0f + __expf(-zf));
    }
}

extern "C" void kernel_launch(void* const* d_in, const int* in_sizes, int n_in,
                              void* d_out, int out_size) {
    const float* x     = (const float*)d_in[0];
    const float* rz_p  = (const float*)d_in[1];
    const float* ry_p  = (const float*)d_in[2];
    const float* ry2_p = (const float*)d_in[3];
    const float* crx_p = (const float*)d_in[4];
    const float* u3_p  = (const float*)d_in[5];
    const float* u3b_p = (const float*)d_in[6];
    const float* W1    = (const float*)d_in[7];
    const float* b1    = (const float*)d_in[8];
    const float* W2    = (const float*)d_in[9];
    const float* b2    = (const float*)d_in[10];

    int B = in_sizes[0] / 32;          // x is (B, 32)
    const int threads = 256;           // 8 warps/block
    int blocks = (B + 7) / 8;
    qcnn_kernel<<<blocks, threads>>>(x, rz_p, ry_p, ry2_p, crx_p, u3_p, u3b_p,
                                     W1, b1, W2, b2, (float*)d_out, B);
}

// round 6
// speedup vs baseline: 1.3333x; 1.3333x over previous
#include <cuda_runtime.h>
#include <cuda_bf16.h>

#define FULL 0xffffffffu
#define R4 0.70710678118654752440f

struct C2 { float x, y; };
__device__ __forceinline__ C2 mkc(float x, float y){ C2 c; c.x=x; c.y=y; return c; }
__device__ __forceinline__ C2 cmul(C2 a, C2 b){
    return mkc(fmaf(a.x,b.x,-a.y*b.y), fmaf(a.x,b.y,a.y*b.x));
}
__device__ __forceinline__ C2 cmadd(C2 a, C2 b, C2 c){  // a*b + c
    return mkc(fmaf(a.x,b.x,fmaf(-a.y,b.y,c.x)), fmaf(a.x,b.y,fmaf(a.y,b.x,c.y)));
}

// Mapping: 16 amplitudes/thread (k bits 0..3), 16 lanes/element (lane bits 0..3),
// element = lane bit 4 (2 elements per warp).
//   odd qubits  (1,3,5,7) -> LOCAL reg bits : q7->k1, q5->k2, q3->k4, q1->k8
//   even qubits (0,2,4,6) -> LANE bits      : q6->l1, q4->l2, q2->l4, q0->l8
template<int Q> struct QM {
    static constexpr bool local = (Q & 1) != 0;
    static constexpr int mask = local ? (1 << ((7 - Q) >> 1)) : (1 << ((6 - Q) >> 1));
};

// ---------------- generic complex 1q gate ----------------
template<int Q>
__device__ __forceinline__ void g1(C2 a[16], C2 u00, C2 u01, C2 u10, C2 u11, int lane){
    constexpr int m = QM<Q>::mask;
    if constexpr (QM<Q>::local) {
        #pragma unroll
        for (int k0 = 0; k0 < 16; ++k0) if (!(k0 & m)) {
            int k1 = k0 | m;
            C2 a0 = a[k0], a1 = a[k1];
            a[k0] = cmadd(u01, a1, cmul(u00, a0));
            a[k1] = cmadd(u11, a1, cmul(u10, a0));
        }
    } else {
        bool hi = (lane & m) != 0;
        C2 cA = hi ? u11 : u00;
        C2 cB = hi ? u10 : u01;
        #pragma unroll
        for (int k = 0; k < 16; ++k) {
            C2 part;
            part.x = __shfl_xor_sync(FULL, a[k].x, m);
            part.y = __shfl_xor_sync(FULL, a[k].y, m);
            a[k] = cmadd(cB, part, cmul(cA, a[k]));
        }
    }
}

// ---------------- RY ----------------
template<int Q>
__device__ __forceinline__ void gry(C2 a[16], float c, float s, int lane){
    constexpr int m = QM<Q>::mask;
    if constexpr (QM<Q>::local) {
        #pragma unroll
        for (int k0 = 0; k0 < 16; ++k0) if (!(k0 & m)) {
            int k1 = k0 | m;
            C2 a0 = a[k0], a1 = a[k1];
            a[k0].x = fmaf(c, a0.x, -s*a1.x); a[k0].y = fmaf(c, a0.y, -s*a1.y);
            a[k1].x = fmaf(s, a0.x,  c*a1.x); a[k1].y = fmaf(s, a0.y,  c*a1.y);
        }
    } else {
        float sg = (lane & m) ? s : -s;
        #pragma unroll
        for (int k = 0; k < 16; ++k) {
            float px = __shfl_xor_sync(FULL, a[k].x, m);
            float py = __shfl_xor_sync(FULL, a[k].y, m);
            a[k].x = fmaf(c, a[k].x, sg*px);
            a[k].y = fmaf(c, a[k].y, sg*py);
        }
    }
}

// ---------------- RZ up to global phase: diag(1, w) ----------------
template<int Q>
__device__ __forceinline__ void grzw(C2 a[16], C2 w, int lane){
    constexpr int m = QM<Q>::mask;
    if constexpr (QM<Q>::local) {
        #pragma unroll
        for (int k = 0; k < 16; ++k) if (k & m) a[k] = cmul(a[k], w);
    } else {
        C2 we = (lane & m) ? w : mkc(1.f, 0.f);
        #pragma unroll
        for (int k = 0; k < 16; ++k) a[k] = cmul(a[k], we);
    }
}

// RZ(∓π/2) up to phase: diag(1, ∓i).  SGN=-1 -> *( -i ), SGN=+1 -> *( +i )
template<int Q, int SGN>
__device__ __forceinline__ void grz_i(C2 a[16], int lane){
    constexpr int m = QM<Q>::mask;
    if constexpr (QM<Q>::local) {
        #pragma unroll
        for (int k = 0; k < 16; ++k) if (k & m) {
            float t = a[k].x;
            if constexpr (SGN < 0) { a[k].x =  a[k].y; a[k].y = -t; }
            else                   { a[k].x = -a[k].y; a[k].y =  t; }
        }
    } else {
        bool hi = (lane & m) != 0;
        #pragma unroll
        for (int k = 0; k < 16; ++k) {
            float nx, ny;
            if constexpr (SGN < 0) { nx =  a[k].y; ny = -a[k].x; }
            else                   { nx = -a[k].y; ny =  a[k].x; }
            a[k].x = hi ? nx : a[k].x;
            a[k].y = hi ? ny : a[k].y;
        }
    }
}

// ---------------- CX ----------------
template<int QC, int QT>
__device__ __forceinline__ void gcx(C2 a[16], int lane){
    constexpr int mc = QM<QC>::mask, mt = QM<QT>::mask;
    if constexpr (QM<QC>::local && QM<QT>::local) {
        #pragma unroll
        for (int k0 = 0; k0 < 16; ++k0) if ((k0 & mc) && !(k0 & mt)) {
            int k1 = k0 | mt; C2 t = a[k0]; a[k0] = a[k1]; a[k1] = t;
        }
    } else if constexpr (QM<QC>::local) { // control local, target lane
        #pragma unroll
        for (int k = 0; k < 16; ++k) if (k & mc) {
            a[k].x = __shfl_xor_sync(FULL, a[k].x, mt);
            a[k].y = __shfl_xor_sync(FULL, a[k].y, mt);
        }
    } else if constexpr (QM<QT>::local) { // control lane, target local
        bool cb = (lane & mc) != 0;
        #pragma unroll
        for (int k0 = 0; k0 < 16; ++k0) if (!(k0 & mt)) {
            int k1 = k0 | mt;
            C2 t0 = a[k0], t1 = a[k1];
            a[k0] = cb ? t1 : t0;
            a[k1] = cb ? t0 : t1;
        }
    } else { // both lane (unused by this circuit)
        bool cb = (lane & mc) != 0;
        #pragma unroll
        for (int k = 0; k < 16; ++k) {
            float px = __shfl_xor_sync(FULL, a[k].x, mt);
            float py = __shfl_xor_sync(FULL, a[k].y, mt);
            if (cb) { a[k].x = px; a[k].y = py; }
        }
    }
}

// ---------------- CRX ----------------
template<int QC, int QT>
__device__ __forceinline__ void gcrx(C2 a[16], float c, float s, int lane){
    constexpr int mc = QM<QC>::mask, mt = QM<QT>::mask;
    if constexpr (QM<QC>::local && QM<QT>::local) {
        #pragma unroll
        for (int k0 = 0; k0 < 16; ++k0) if ((k0 & mc) && !(k0 & mt)) {
            int k1 = k0 | mt;
            C2 a0 = a[k0], a1 = a[k1];
            a[k0].x = fmaf(c, a0.x,  s*a1.y); a[k0].y = fmaf(c, a0.y, -s*a1.x);
            a[k1].x = fmaf(c, a1.x,  s*a0.y); a[k1].y = fmaf(c, a1.y, -s*a0.x);
        }
    } else if constexpr (QM<QC>::local) { // control local, target lane
        #pragma unroll
        for (int k = 0; k < 16; ++k) if (k & mc) {
            float px = __shfl_xor_sync(FULL, a[k].x, mt);
            float py = __shfl_xor_sync(FULL, a[k].y, mt);
            float nx = fmaf(c, a[k].x,  s*py);
            float ny = fmaf(c, a[k].y, -s*px);
            a[k].x = nx; a[k].y = ny;
        }
    } else if constexpr (QM<QT>::local) { // control lane, target local
        bool cb = (lane & mc) != 0;
        float ce = cb ? c : 1.0f;
        float se = cb ? s : 0.0f;
        #pragma unroll
        for (int k0 = 0; k0 < 16; ++k0) if (!(k0 & mt)) {
            int k1 = k0 | mt;
            C2 a0 = a[k0], a1 = a[k1];
            a[k0].x = fmaf(ce, a0.x,  se*a1.y); a[k0].y = fmaf(ce, a0.y, -se*a1.x);
            a[k1].x = fmaf(ce, a1.x,  se*a0.y); a[k1].y = fmaf(ce, a1.y, -se*a0.x);
        }
    } else { // both lane (unused)
        bool cb = (lane & mc) != 0;
        float ce = cb ? c : 1.0f;
        float se = cb ? s : 0.0f;
        #pragma unroll
        for (int k = 0; k < 16; ++k) {
            float px = __shfl_xor_sync(FULL, a[k].x, mt);
            float py = __shfl_xor_sync(FULL, a[k].y, mt);
            float nx = fmaf(ce, a[k].x,  se*py);
            float ny = fmaf(ce, a[k].y, -se*px);
            a[k].x = nx; a[k].y = ny;
        }
    }
}

// ---------------- real-state versions (encode: RY + CX only) ----------------
template<int Q>
__device__ __forceinline__ void gryR(float r[16], float c, float s, int lane){
    constexpr int m = QM<Q>::mask;
    if constexpr (QM<Q>::local) {
        #pragma unroll
        for (int k0 = 0; k0 < 16; ++k0) if (!(k0 & m)) {
            int k1 = k0 | m;
            float a0 = r[k0], a1 = r[k1];
            r[k0] = fmaf(c, a0, -s*a1);
            r[k1] = fmaf(s, a0,  c*a1);
        }
    } else {
        float sg = (lane & m) ? s : -s;
        #pragma unroll
        for (int k = 0; k < 16; ++k) {
            float pv = __shfl_xor_sync(FULL, r[k], m);
            r[k] = fmaf(c, r[k], sg*pv);
        }
    }
}

template<int QC, int QT>
__device__ __forceinline__ void gcxR(float r[16], int lane){
    constexpr int mc = QM<QC>::mask, mt = QM<QT>::mask;
    if constexpr (QM<QC>::local && QM<QT>::local) {
        #pragma unroll
        for (int k0 = 0; k0 < 16; ++k0) if ((k0 & mc) && !(k0 & mt)) {
            int k1 = k0 | mt; float t = r[k0]; r[k0] = r[k1]; r[k1] = t;
        }
    } else if constexpr (QM<QC>::local) {
        #pragma unroll
        for (int k = 0; k < 16; ++k) if (k & mc)
            r[k] = __shfl_xor_sync(FULL, r[k], mt);
    } else if constexpr (QM<QT>::local) {
        bool cb = (lane & mc) != 0;
        #pragma unroll
        for (int k0 = 0; k0 < 16; ++k0) if (!(k0 & mt)) {
            int k1 = k0 | mt;
            float t0 = r[k0], t1 = r[k1];
            r[k0] = cb ? t1 : t0;
            r[k1] = cb ? t0 : t1;
        }
    } else {
        bool cb = (lane & mc) != 0;
        #pragma unroll
        for (int k = 0; k < 16; ++k) {
            float pv = __shfl_xor_sync(FULL, r[k], mt);
            r[k] = cb ? pv : r[k];
        }
    }
}

// sum within each 16-lane half of the warp
__device__ __forceinline__ float wsum16(float v){
    #pragma unroll
    for (int o = 8; o; o >>= 1) v += __shfl_xor_sync(FULL, v, o);
    return v;
}

__global__ void __launch_bounds__(128)
qcnn_kernel(const float* __restrict__ x,
            const float* __restrict__ rz_p,  const float* __restrict__ ry_p,
            const float* __restrict__ ry2_p, const float* __restrict__ crx_p,
            const float* __restrict__ u3_p,  const float* __restrict__ u3b_p,
            const float* __restrict__ W1,    const float* __restrict__ b1,
            const float* __restrict__ W2,    const float* __restrict__ b2,
            float* __restrict__ out, int B)
{
    const int warp = (blockIdx.x * blockDim.x + threadIdx.x) >> 5;
    const int lane = threadIdx.x & 31;
    const int hl   = lane & 15;
    const int elem = warp * 2 + (lane >> 4);
    if (warp * 2 >= B) return;               // whole-warp uniform exit
    const int e = (elem < B) ? elem : (B - 1);

    // ================= encode (state purely REAL) =================
    // Each half-warp owns one element; each lane holds angles 2*hl, 2*hl+1.
    float2 av = reinterpret_cast<const float2*>(x)[e * 16 + hl];
    float c0, s0, c1, s1;
    __sincosf(0.5f * av.x, &s0, &c0);
    __sincosf(0.5f * av.y, &s1, &c1);

    float r[16];
    #pragma unroll
    for (int k = 0; k < 16; ++k) r[k] = 0.0f;
    r[0] = (hl == 0) ? 1.0f : 0.0f;

    #define RYQ(CY,Q) do { \
        const int idx_ = (CY)*8 + (Q); \
        int src_ = (lane & 16) | (idx_ >> 1); \
        float cc_ = __shfl_sync(FULL, ((idx_ & 1) ? c1 : c0), src_); \
        float ss_ = __shfl_sync(FULL, ((idx_ & 1) ? s1 : s0), src_); \
        gryR<Q>(r, cc_, ss_, lane); } while(0)

    #define ENC_CYC(CY) \
        RYQ(CY,0); RYQ(CY,1); RYQ(CY,2); RYQ(CY,3); \
        RYQ(CY,4); RYQ(CY,5); RYQ(CY,6); RYQ(CY,7); \
        gcxR<0,1>(r,lane); gcxR<1,2>(r,lane); gcxR<2,3>(r,lane); gcxR<3,4>(r,lane); \
        gcxR<4,5>(r,lane); gcxR<5,6>(r,lane); gcxR<6,7>(r,lane); gcxR<7,0>(r,lane);

    ENC_CYC(0) ENC_CYC(1) ENC_CYC(2) ENC_CYC(3)

    // ================= psi0 parameters =================
    // RZ(t) applied as diag(1, e^{it}) (global phase dropped — only |amp|^2 measured)
    C2 wz[2];
    float yc[2], ys[2], y2c[2], y2s[2];
    C2 A00[2], A01[2], A10[2], A11[2];
    #pragma unroll
    for (int l = 0; l < 2; ++l) {
        float zs, zc;
        __sincosf(rz_p[l], &zs, &zc);
        wz[l] = mkc(zc, zs);
        __sincosf(ry_p[l]  * 0.5f, &ys[l],  &yc[l]);
        __sincosf(ry2_p[l] * 0.5f, &y2s[l], &y2c[l]);
        float t = u3_p[l*3+0], ph = u3_p[l*3+1], la = u3_p[l*3+2];
        float st, ct, sp, cp, sl, cl, spl, cpl;
        __sincosf(t * 0.5f, &st, &ct);
        __sincosf(ph, &sp, &cp);
        __sincosf(la, &sl, &cl);
        __sincosf(ph + la, &spl, &cpl);
        A00[l] = mkc(ct, 0.f);
        A01[l] = mkc(-cl*st, -sl*st);
        A10[l] = mkc( cp*st,  sp*st);
        A11[l] = mkc(cpl*ct, spl*ct);
    }

    // ================= psi0 circuit =================
    C2 a[16];
    #pragma unroll
    for (int k = 0; k < 16; ++k) a[k] = mkc(r[k], 0.f);

    #define BLK(QC,QT,L) \
        grz_i<QT,-1>(a, lane); \
        gcx<QT,QC>(a, lane); \
        grzw<QC>(a, wz[L], lane); \
        gry<QT>(a, yc[L], ys[L], lane); \
        gcx<QC,QT>(a, lane); \
        gry<QT>(a, y2c[L], y2s[L], lane); \
        gcx<QT,QC>(a, lane); \
        grz_i<QC,+1>(a, lane);

    BLK(0,1,0) BLK(2,3,0) BLK(4,5,0) BLK(6,7,0)
    BLK(1,2,0) BLK(3,4,0) BLK(5,6,0)
    g1<1>(a, A00[0], A01[0], A10[0], A11[0], lane);
    g1<3>(a, A00[0], A01[0], A10[0], A11[0], lane);
    g1<5>(a, A00[0], A01[0], A10[0], A11[0], lane);
    g1<7>(a, A00[0], A01[0], A10[0], A11[0], lane);
    BLK(1,3,1) BLK(5,7,1) BLK(3,5,1)
    g1<3>(a, A00[1], A01[1], A10[1], A11[1], lane);
    g1<7>(a, A00[1], A01[1], A10[1], A11[1], lane);

    // measure psi0: qubit3 -> k bit2 (mask 4), qubit7 -> k bit0 (mask 1)
    float p3 = 0.f, p7 = 0.f;
    #pragma unroll
    for (int k = 0; k < 16; ++k) {
        float m = fmaf(a[k].x, a[k].x, a[k].y * a[k].y);
        p3 += (k & 4) ? -m : m;
        p7 += (k & 1) ? -m : m;
    }
    float f0 = wsum16(p3);
    float f1 = wsum16(p7);

    // ================= psi1 parameters =================
    float xcf[2], xsf[2];
    C2 B00[2], B01[2], B10[2], B11[2];
    #pragma unroll
    for (int l = 0; l < 2; ++l) {
        __sincosf(crx_p[l] * 0.5f, &xsf[l], &xcf[l]);
        float t = u3b_p[l*3+0], ph = u3b_p[l*3+1], la = u3b_p[l*3+2];
        float st, ct, sp, cp, sl, cl, spl, cpl;
        __sincosf(t * 0.5f, &st, &ct);
        __sincosf(ph, &sp, &cp);
        __sincosf(la, &sl, &cl);
        __sincosf(ph + la, &spl, &cpl);
        B00[l] = mkc(ct, 0.f);
        B01[l] = mkc(-cl*st, -sl*st);
        B10[l] = mkc( cp*st,  sp*st);
        B11[l] = mkc(cpl*ct, spl*ct);
    }

    // ================= psi1 circuit =================
    #pragma unroll
    for (int k = 0; k < 16; ++k) a[k] = mkc(r[k], 0.f);

    gcrx<0,1>(a, xcf[0], xsf[0], lane);
    gcrx<2,3>(a, xcf[0], xsf[0], lane);
    gcrx<4,5>(a, xcf[0], xsf[0], lane);
    gcrx<6,7>(a, xcf[0], xsf[0], lane);
    gcrx<1,2>(a, xcf[0], xsf[0], lane);
    gcrx<3,4>(a, xcf[0], xsf[0], lane);
    gcrx<5,6>(a, xcf[0], xsf[0], lane);
    g1<1>(a, B00[0], B01[0], B10[0], B11[0], lane);
    g1<3>(a, B00[0], B01[0], B10[0], B11[0], lane);
    g1<5>(a, B00[0], B01[0], B10[0], B11[0], lane);
    g1<7>(a, B00[0], B01[0], B10[0], B11[0], lane);
    gcrx<1,3>(a, xcf[1], xsf[1], lane);
    gcrx<5,7>(a, xcf[1], xsf[1], lane);
    gcrx<3,5>(a, xcf[1], xsf[1], lane);
    g1<3>(a, B00[1], B01[1], B10[1], B11[1], lane);
    g1<7>(a, B00[1], B01[1], B10[1], B11[1], lane);

    // measure psi1
    p3 = 0.f; p7 = 0.f;
    #pragma unroll
    for (int k = 0; k < 16; ++k) {
        float m = fmaf(a[k].x, a[k].x, a[k].y * a[k].y);
        p3 += (k & 4) ? -m : m;
        p7 += (k & 1) ? -m : m;
    }
    float f2 = wsum16(p3);
    float f3 = wsum16(p7);

    // ================= MLP head =================
    float hv = 0.f;
    if (hl < 15) {
        float z = b1[hl];
        z = fmaf(W1[hl*4+0], f0, z);
        z = fmaf(W1[hl*4+1], f1, z);
        z = fmaf(W1[hl*4+2], f2, z);
        z = fmaf(W1[hl*4+3], f3, z);
        hv = tanhf(z) * W2[hl];
    }
    float s = wsum16(hv);
    if (hl == 0 && elem < B) {
        float zf = s + b2[0];
        out[elem] = 1.0f / (1.0f + __expf(-zf));
    }
}

extern "C" void kernel_launch(void* const* d_in, const int* in_sizes, int n_in,
                              void* d_out, int out_size) {
    const float* x     = (const float*)d_in[0];
    const float* rz_p  = (const float*)d_in[1];
    const float* ry_p  = (const float*)d_in[2];
    const float* ry2_p = (const float*)d_in[3];
    const float* crx_p = (const float*)d_in[4];
    const float* u3_p  = (const float*)d_in[5];
    const float* u3b_p = (const float*)d_in[6];
    const float* W1    = (const float*)d_in[7];
    const float* b1    = (const float*)d_in[8];
    const float* W2    = (const float*)d_in[9];
    const float* b2    = (const float*)d_in[10];

    int B = in_sizes[0] / 32;          // x is (B, 32)
    const int threads = 128;           // 4 warps/block, 8 elements/block
    int blocks = (B + 7) / 8;
    qcnn_kernel<<<blocks, threads>>>(x, rz_p, ry_p, ry2_p, crx_p, u3_p, u3b_p,
                                     W1, b1, W2, b2, (float*)d_out, B);
}

// round 7
// speedup vs baseline: 1.4617x; 1.0963x over previous
#include <cuda_runtime.h>
#include <cuda_bf16.h>

#define FULL 0xffffffffu

struct C2 { float x, y; };
__device__ __forceinline__ C2 mkc(float x, float y){ C2 c; c.x=x; c.y=y; return c; }
#define DUP(s) mkc((s),(s))

// ---------- packed f32x2 elementwise ops (FFMA2 path, sm_100+) ----------
__device__ __forceinline__ C2 pfma(C2 a, C2 b, C2 c){  // per-component a*b+c
    C2 r;
    asm("{\n\t.reg .b64 A,B,C,D;\n\t"
        "mov.b64 A,{%2,%3};\n\t"
        "mov.b64 B,{%4,%5};\n\t"
        "mov.b64 C,{%6,%7};\n\t"
        "fma.rn.f32x2 D, A, B, C;\n\t"
        "mov.b64 {%0,%1}, D;\n\t}"
        : "=f"(r.x), "=f"(r.y)
        : "f"(a.x), "f"(a.y), "f"(b.x), "f"(b.y), "f"(c.x), "f"(c.y));
    return r;
}
__device__ __forceinline__ C2 pmul(C2 a, C2 b){        // per-component a*b
    C2 r;
    asm("{\n\t.reg .b64 A,B,D;\n\t"
        "mov.b64 A,{%2,%3};\n\t"
        "mov.b64 B,{%4,%5};\n\t"
        "mul.rn.f32x2 D, A, B;\n\t"
        "mov.b64 {%0,%1}, D;\n\t}"
        : "=f"(r.x), "=f"(r.y)
        : "f"(a.x), "f"(a.y), "f"(b.x), "f"(b.y));
    return r;
}

// Mapping: 16 amplitudes/thread (k bits 0..3), 16 lanes/element (lane bits 0..3),
// element = lane bit 4 (2 elements per warp).
//   odd qubits  (1,3,5,7) -> LOCAL reg bits : q7->k1, q5->k2, q3->k4, q1->k8
//   even qubits (0,2,4,6) -> LANE bits      : q6->l1, q4->l2, q2->l4, q0->l8
template<int Q> struct QM {
    static constexpr bool local = (Q & 1) != 0;
    static constexpr int mask = local ? (1 << ((7 - Q) >> 1)) : (1 << ((6 - Q) >> 1));
};

// ---------------- generic complex 1q gate (packed) ----------------
template<int Q>
__device__ __forceinline__ void g1(C2 a[16], C2 u00, C2 u01, C2 u10, C2 u11, int lane){
    constexpr int m = QM<Q>::mask;
    if constexpr (QM<Q>::local) {
        C2 x00 = DUP(u00.x), y00 = mkc(-u00.y, u00.y);
        C2 x01 = DUP(u01.x), y01 = mkc(-u01.y, u01.y);
        C2 x10 = DUP(u10.x), y10 = mkc(-u10.y, u10.y);
        C2 x11 = DUP(u11.x), y11 = mkc(-u11.y, u11.y);
        #pragma unroll
        for (int k0 = 0; k0 < 16; ++k0) if (!(k0 & m)) {
            int k1 = k0 | m;
            C2 a0 = a[k0], a1 = a[k1];
            C2 a0s = mkc(a0.y, a0.x), a1s = mkc(a1.y, a1.x);
            C2 t0 = pmul(x00, a0); t0 = pfma(y00, a0s, t0);
            t0 = pfma(x01, a1, t0); t0 = pfma(y01, a1s, t0);
            C2 t1 = pmul(x10, a0); t1 = pfma(y10, a0s, t1);
            t1 = pfma(x11, a1, t1); t1 = pfma(y11, a1s, t1);
            a[k0] = t0; a[k1] = t1;
        }
    } else {
        bool hi = (lane & m) != 0;
        C2 xA = hi ? DUP(u11.x) : DUP(u00.x);
        C2 yA = hi ? mkc(-u11.y, u11.y) : mkc(-u00.y, u00.y);
        C2 xB = hi ? DUP(u10.x) : DUP(u01.x);
        C2 yB = hi ? mkc(-u10.y, u10.y) : mkc(-u01.y, u01.y);
        #pragma unroll
        for (int k = 0; k < 16; ++k) {
            float px = __shfl_xor_sync(FULL, a[k].x, m);
            float py = __shfl_xor_sync(FULL, a[k].y, m);
            C2 as_ = mkc(a[k].y, a[k].x);
            C2 t = pmul(xA, a[k]); t = pfma(yA, as_, t);
            t = pfma(xB, mkc(px, py), t); t = pfma(yB, mkc(py, px), t);
            a[k] = t;
        }
    }
}

// ---------------- RY (packed: identical real coeffs per component) ----------------
template<int Q>
__device__ __forceinline__ void gry(C2 a[16], float c, float s, int lane){
    constexpr int m = QM<Q>::mask;
    C2 c2 = DUP(c);
    if constexpr (QM<Q>::local) {
        C2 s2 = DUP(s), ns2 = DUP(-s);
        #pragma unroll
        for (int k0 = 0; k0 < 16; ++k0) if (!(k0 & m)) {
            int k1 = k0 | m;
            C2 a0 = a[k0], a1 = a[k1];
            a[k0] = pfma(c2, a0, pmul(ns2, a1));
            a[k1] = pfma(s2, a0, pmul(c2, a1));
        }
    } else {
        C2 sg2 = (lane & m) ? DUP(s) : DUP(-s);
        #pragma unroll
        for (int k = 0; k < 16; ++k) {
            C2 p;
            p.x = __shfl_xor_sync(FULL, a[k].x, m);
            p.y = __shfl_xor_sync(FULL, a[k].y, m);
            a[k] = pfma(c2, a[k], pmul(sg2, p));
        }
    }
}

// ---------------- RZ up to global phase: diag(1, w) (packed cmul) ----------------
template<int Q>
__device__ __forceinline__ void grzw(C2 a[16], C2 w, int lane){
    constexpr int m = QM<Q>::mask;
    C2 wx2 = DUP(w.x);
    C2 wy2 = mkc(-w.y, w.y);
    if constexpr (QM<Q>::local) {
        #pragma unroll
        for (int k = 0; k < 16; ++k) if (k & m)
            a[k] = pfma(wy2, mkc(a[k].y, a[k].x), pmul(wx2, a[k]));
    } else {
        C2 ex2 = (lane & m) ? wx2 : DUP(1.f);
        C2 ey2 = (lane & m) ? wy2 : DUP(0.f);
        #pragma unroll
        for (int k = 0; k < 16; ++k)
            a[k] = pfma(ey2, mkc(a[k].y, a[k].x), pmul(ex2, a[k]));
    }
}

// RZ(∓π/2) up to phase: diag(1, ∓i)
template<int Q, int SGN>
__device__ __forceinline__ void grz_i(C2 a[16], int lane){
    constexpr int m = QM<Q>::mask;
    if constexpr (QM<Q>::local) {
        #pragma unroll
        for (int k = 0; k < 16; ++k) if (k & m) {
            float t = a[k].x;
            if constexpr (SGN < 0) { a[k].x =  a[k].y; a[k].y = -t; }
            else                   { a[k].x = -a[k].y; a[k].y =  t; }
        }
    } else {
        bool hi = (lane & m) != 0;
        #pragma unroll
        for (int k = 0; k < 16; ++k) {
            float nx, ny;
            if constexpr (SGN < 0) { nx =  a[k].y; ny = -a[k].x; }
            else                   { nx = -a[k].y; ny =  a[k].x; }
            a[k].x = hi ? nx : a[k].x;
            a[k].y = hi ? ny : a[k].y;
        }
    }
}

// ---------------- CX ----------------
template<int QC, int QT>
__device__ __forceinline__ void gcx(C2 a[16], int lane){
    constexpr int mc = QM<QC>::mask, mt = QM<QT>::mask;
    if constexpr (QM<QC>::local && QM<QT>::local) {
        #pragma unroll
        for (int k0 = 0; k0 < 16; ++k0) if ((k0 & mc) && !(k0 & mt)) {
            int k1 = k0 | mt; C2 t = a[k0]; a[k0] = a[k1]; a[k1] = t;
        }
    } else if constexpr (QM<QC>::local) { // control local, target lane
        #pragma unroll
        for (int k = 0; k < 16; ++k) if (k & mc) {
            a[k].x = __shfl_xor_sync(FULL, a[k].x, mt);
            a[k].y = __shfl_xor_sync(FULL, a[k].y, mt);
        }
    } else if constexpr (QM<QT>::local) { // control lane, target local
        bool cb = (lane & mc) != 0;
        #pragma unroll
        for (int k0 = 0; k0 < 16; ++k0) if (!(k0 & mt)) {
            int k1 = k0 | mt;
            C2 t0 = a[k0], t1 = a[k1];
            a[k0] = cb ? t1 : t0;
            a[k1] = cb ? t0 : t1;
        }
    } else { // both lane (unused by this circuit)
        bool cb = (lane & mc) != 0;
        #pragma unroll
        for (int k = 0; k < 16; ++k) {
            float px = __shfl_xor_sync(FULL, a[k].x, mt);
            float py = __shfl_xor_sync(FULL, a[k].y, mt);
            if (cb) { a[k].x = px; a[k].y = py; }
        }
    }
}

// ---------------- CRX (packed): a0' = c*a0 + s*(a1.y, -a1.x) ----------------
template<int QC, int QT>
__device__ __forceinline__ void gcrx(C2 a[16], float c, float s, int lane){
    constexpr int mc = QM<QC>::mask, mt = QM<QT>::mask;
    if constexpr (QM<QC>::local && QM<QT>::local) {
        C2 c2 = DUP(c), sn = mkc(s, -s);
        #pragma unroll
        for (int k0 = 0; k0 < 16; ++k0) if ((k0 & mc) && !(k0 & mt)) {
            int k1 = k0 | mt;
            C2 a0 = a[k0], a1 = a[k1];
            a[k0] = pfma(c2, a0, pmul(sn, mkc(a1.y, a1.x)));
            a[k1] = pfma(c2, a1, pmul(sn, mkc(a0.y, a0.x)));
        }
    } else if constexpr (QM<QC>::local) { // control local, target lane
        C2 c2 = DUP(c), sn = mkc(s, -s);
        #pragma unroll
        for (int k = 0; k < 16; ++k) if (k & mc) {
            float px = __shfl_xor_sync(FULL, a[k].x, mt);
            float py = __shfl_xor_sync(FULL, a[k].y, mt);
            a[k] = pfma(c2, a[k], pmul(sn, mkc(py, px)));
        }
    } else if constexpr (QM<QT>::local) { // control lane, target local
        bool cb = (lane & mc) != 0;
        C2 c2 = DUP(cb ? c : 1.0f);
        C2 sn = cb ? mkc(s, -s) : mkc(0.f, 0.f);
        #pragma unroll
        for (int k0 = 0; k0 < 16; ++k0) if (!(k0 & mt)) {
            int k1 = k0 | mt;
            C2 a0 = a[k0], a1 = a[k1];
            a[k0] = pfma(c2, a0, pmul(sn, mkc(a1.y, a1.x)));
            a[k1] = pfma(c2, a1, pmul(sn, mkc(a0.y, a0.x)));
        }
    } else { // both lane (unused)
        bool cb = (lane & mc) != 0;
        C2 c2 = DUP(cb ? c : 1.0f);
        C2 sn = cb ? mkc(s, -s) : mkc(0.f, 0.f);
        #pragma unroll
        for (int k = 0; k < 16; ++k) {
            float px = __shfl_xor_sync(FULL, a[k].x, mt);
            float py = __shfl_xor_sync(FULL, a[k].y, mt);
            a[k] = pfma(c2, a[k], pmul(sn, mkc(py, px)));
        }
    }
}

// ---------------- real-state encode gates (packed over adjacent k-pairs) ----------------
template<int Q>
__device__ __forceinline__ void gryR(float r[16], float c, float s, int lane){
    constexpr int m = QM<Q>::mask;
    C2 c2 = DUP(c);
    if constexpr (QM<Q>::local) {
        if constexpr (m == 1) {
            // within-pair butterfly: (c r0 - s r1, c r1 + s r0)
            C2 snn = mkc(-s, s);
            #pragma unroll
            for (int j = 0; j < 8; ++j) {
                C2 v = mkc(r[2*j], r[2*j+1]);
                C2 res = pfma(snn, mkc(v.y, v.x), pmul(c2, v));
                r[2*j] = res.x; r[2*j+1] = res.y;
            }
        } else {
            constexpr int pm = m >> 1;
            C2 s2 = DUP(s), ns2 = DUP(-s);
            #pragma unroll
            for (int j0 = 0; j0 < 8; ++j0) if (!(j0 & pm)) {
                int j1 = j0 | pm;
                C2 v0 = mkc(r[2*j0], r[2*j0+1]);
                C2 v1 = mkc(r[2*j1], r[2*j1+1]);
                C2 n0 = pfma(c2, v0, pmul(ns2, v1));
                C2 n1 = pfma(s2, v0, pmul(c2, v1));
                r[2*j0] = n0.x; r[2*j0+1] = n0.y;
                r[2*j1] = n1.x; r[2*j1+1] = n1.y;
            }
        }
    } else {
        C2 sg2 = (lane & m) ? DUP(s) : DUP(-s);
        #pragma unroll
        for (int j = 0; j < 8; ++j) {
            float px = __shfl_xor_sync(FULL, r[2*j],   m);
            float py = __shfl_xor_sync(FULL, r[2*j+1], m);
            C2 v = mkc(r[2*j], r[2*j+1]);
            C2 res = pfma(c2, v, pmul(sg2, mkc(px, py)));
            r[2*j] = res.x; r[2*j+1] = res.y;
        }
    }
}

template<int QC, int QT>
__device__ __forceinline__ void gcxR(float r[16], int lane){
    constexpr int mc = QM<QC>::mask, mt = QM<QT>::mask;
    if constexpr (QM<QC>::local && QM<QT>::local) {
        #pragma unroll
        for (int k0 = 0; k0 < 16; ++k0) if ((k0 & mc) && !(k0 & mt)) {
            int k1 = k0 | mt; float t = r[k0]; r[k0] = r[k1]; r[k1] = t;
        }
    } else if constexpr (QM<QC>::local) {
        #pragma unroll
        for (int k = 0; k < 16; ++k) if (k & mc)
            r[k] = __shfl_xor_sync(FULL, r[k], mt);
    } else if constexpr (QM<QT>::local) {
        bool cb = (lane & mc) != 0;
        #pragma unroll
        for (int k0 = 0; k0 < 16; ++k0) if (!(k0 & mt)) {
            int k1 = k0 | mt;
            float t0 = r[k0], t1 = r[k1];
            r[k0] = cb ? t1 : t0;
            r[k1] = cb ? t0 : t1;
        }
    } else {
        bool cb = (lane & mc) != 0;
        #pragma unroll
        for (int k = 0; k < 16; ++k) {
            float pv = __shfl_xor_sync(FULL, r[k], mt);
            r[k] = cb ? pv : r[k];
        }
    }
}

// sum within each 16-lane half of the warp
__device__ __forceinline__ float wsum16(float v){
    #pragma unroll
    for (int o = 8; o; o >>= 1) v += __shfl_xor_sync(FULL, v, o);
    return v;
}

__global__ void __launch_bounds__(128)
qcnn_kernel(const float* __restrict__ x,
            const float* __restrict__ rz_p,  const float* __restrict__ ry_p,
            const float* __restrict__ ry2_p, const float* __restrict__ crx_p,
            const float* __restrict__ u3_p,  const float* __restrict__ u3b_p,
            const float* __restrict__ W1,    const float* __restrict__ b1,
            const float* __restrict__ W2,    const float* __restrict__ b2,
            float* __restrict__ out, int B)
{
    const int warp = (blockIdx.x * blockDim.x + threadIdx.x) >> 5;
    const int lane = threadIdx.x & 31;
    const int hl   = lane & 15;
    const int elem = warp * 2 + (lane >> 4);
    if (warp * 2 >= B) return;               // whole-warp uniform exit
    const int e = (elem < B) ? elem : (B - 1);

    // ================= encode (state purely REAL) =================
    float2 av = reinterpret_cast<const float2*>(x)[e * 16 + hl];
    float c0, s0, c1, s1;
    __sincosf(0.5f * av.x, &s0, &c0);
    __sincosf(0.5f * av.y, &s1, &c1);

    float r[16];
    #pragma unroll
    for (int k = 0; k < 16; ++k) r[k] = 0.0f;
    r[0] = (hl == 0) ? 1.0f : 0.0f;

    #define RYQ(CY,Q) do { \
        const int idx_ = (CY)*8 + (Q); \
        int src_ = (lane & 16) | (idx_ >> 1); \
        float cc_ = __shfl_sync(FULL, ((idx_ & 1) ? c1 : c0), src_); \
        float ss_ = __shfl_sync(FULL, ((idx_ & 1) ? s1 : s0), src_); \
        gryR<Q>(r, cc_, ss_, lane); } while(0)

    #define ENC_CYC(CY) \
        RYQ(CY,0); RYQ(CY,1); RYQ(CY,2); RYQ(CY,3); \
        RYQ(CY,4); RYQ(CY,5); RYQ(CY,6); RYQ(CY,7); \
        gcxR<0,1>(r,lane); gcxR<1,2>(r,lane); gcxR<2,3>(r,lane); gcxR<3,4>(r,lane); \
        gcxR<4,5>(r,lane); gcxR<5,6>(r,lane); gcxR<6,7>(r,lane); gcxR<7,0>(r,lane);

    ENC_CYC(0) ENC_CYC(1) ENC_CYC(2) ENC_CYC(3)

    // ================= psi0 parameters =================
    C2 wz[2];
    float yc[2], ys[2], y2c[2], y2s[2];
    C2 A00[2], A01[2], A10[2], A11[2];
    #pragma unroll
    for (int l = 0; l < 2; ++l) {
        float zs, zc;
        __sincosf(rz_p[l], &zs, &zc);
        wz[l] = mkc(zc, zs);
        __sincosf(ry_p[l]  * 0.5f, &ys[l],  &yc[l]);
        __sincosf(ry2_p[l] * 0.5f, &y2s[l], &y2c[l]);
        float t = u3_p[l*3+0], ph = u3_p[l*3+1], la = u3_p[l*3+2];
        float st, ct, sp, cp, sl, cl, spl, cpl;
        __sincosf(t * 0.5f, &st, &ct);
        __sincosf(ph, &sp, &cp);
        __sincosf(la, &sl, &cl);
        __sincosf(ph + la, &spl, &cpl);
        A00[l] = mkc(ct, 0.f);
        A01[l] = mkc(-cl*st, -sl*st);
        A10[l] = mkc( cp*st,  sp*st);
        A11[l] = mkc(cpl*ct, spl*ct);
    }

    // ================= psi0 circuit =================
    C2 a[16];
    #pragma unroll
    for (int k = 0; k < 16; ++k) a[k] = mkc(r[k], 0.f);

    #define BLK(QC,QT,L) \
        grz_i<QT,-1>(a, lane); \
        gcx<QT,QC>(a, lane); \
        grzw<QC>(a, wz[L], lane); \
        gry<QT>(a, yc[L], ys[L], lane); \
        gcx<QC,QT>(a, lane); \
        gry<QT>(a, y2c[L], y2s[L], lane); \
        gcx<QT,QC>(a, lane); \
        grz_i<QC,+1>(a, lane);

    BLK(0,1,0) BLK(2,3,0) BLK(4,5,0) BLK(6,7,0)
    BLK(1,2,0) BLK(3,4,0) BLK(5,6,0)
    g1<1>(a, A00[0], A01[0], A10[0], A11[0], lane);
    g1<3>(a, A00[0], A01[0], A10[0], A11[0], lane);
    g1<5>(a, A00[0], A01[0], A10[0], A11[0], lane);
    g1<7>(a, A00[0], A01[0], A10[0], A11[0], lane);
    BLK(1,3,1) BLK(5,7,1) BLK(3,5,1)
    g1<3>(a, A00[1], A01[1], A10[1], A11[1], lane);
    g1<7>(a, A00[1], A01[1], A10[1], A11[1], lane);

    // measure psi0: qubit3 -> k bit2 (mask 4), qubit7 -> k bit0 (mask 1)
    float p3 = 0.f, p7 = 0.f;
    #pragma unroll
    for (int k = 0; k < 16; ++k) {
        float m = fmaf(a[k].x, a[k].x, a[k].y * a[k].y);
        p3 += (k & 4) ? -m : m;
        p7 += (k & 1) ? -m : m;
    }
    float f0 = wsum16(p3);
    float f1 = wsum16(p7);

    // ================= psi1 parameters =================
    float xcf[2], xsf[2];
    C2 B00[2], B01[2], B10[2], B11[2];
    #pragma unroll
    for (int l = 0; l < 2; ++l) {
        __sincosf(crx_p[l] * 0.5f, &xsf[l], &xcf[l]);
        float t = u3b_p[l*3+0], ph = u3b_p[l*3+1], la = u3b_p[l*3+2];
        float st, ct, sp, cp, sl, cl, spl, cpl;
        __sincosf(t * 0.5f, &st, &ct);
        __sincosf(ph, &sp, &cp);
        __sincosf(la, &sl, &cl);
        __sincosf(ph + la, &spl, &cpl);
        B00[l] = mkc(ct, 0.f);
        B01[l] = mkc(-cl*st, -sl*st);
        B10[l] = mkc( cp*st,  sp*st);
        B11[l] = mkc(cpl*ct, spl*ct);
    }

    // ================= psi1 circuit =================
    #pragma unroll
    for (int k = 0; k < 16; ++k) a[k] = mkc(r[k], 0.f);

    gcrx<0,1>(a, xcf[0], xsf[0], lane);
    gcrx<2,3>(a, xcf[0], xsf[0], lane);
    gcrx<4,5>(a, xcf[0], xsf[0], lane);
    gcrx<6,7>(a, xcf[0], xsf[0], lane);
    gcrx<1,2>(a, xcf[0], xsf[0], lane);
    gcrx<3,4>(a, xcf[0], xsf[0], lane);
    gcrx<5,6>(a, xcf[0], xsf[0], lane);
    g1<1>(a, B00[0], B01[0], B10[0], B11[0], lane);
    g1<3>(a, B00[0], B01[0], B10[0], B11[0], lane);
    g1<5>(a, B00[0], B01[0], B10[0], B11[0], lane);
    g1<7>(a, B00[0], B01[0], B10[0], B11[0], lane);
    gcrx<1,3>(a, xcf[1], xsf[1], lane);
    gcrx<5,7>(a, xcf[1], xsf[1], lane);
    gcrx<3,5>(a, xcf[1], xsf[1], lane);
    g1<3>(a, B00[1], B01[1], B10[1], B11[1], lane);
    g1<7>(a, B00[1], B01[1], B10[1], B11[1], lane);

    // measure psi1
    p3 = 0.f; p7 = 0.f;
    #pragma unroll
    for (int k = 0; k < 16; ++k) {
        float m = fmaf(a[k].x, a[k].x, a[k].y * a[k].y);
        p3 += (k & 4) ? -m : m;
        p7 += (k & 1) ? -m : m;
    }
    float f2 = wsum16(p3);
    float f3 = wsum16(p7);

    // ================= MLP head =================
    float hv = 0.f;
    if (hl < 15) {
        float z = b1[hl];
        z = fmaf(W1[hl*4+0], f0, z);
        z = fmaf(W1[hl*4+1], f1, z);
        z = fmaf(W1[hl*4+2], f2, z);
        z = fmaf(W1[hl*4+3], f3, z);
        hv = tanhf(z) * W2[hl];
    }
    float s = wsum16(hv);
    if (hl == 0 && elem < B) {
        float zf = s + b2[0];
        out[elem] = 1.0f / (1.0f + __expf(-zf));
    }
}

extern "C" void kernel_launch(void* const* d_in, const int* in_sizes, int n_in,
                              void* d_out, int out_size) {
    const float* x     = (const float*)d_in[0];
    const float* rz_p  = (const float*)d_in[1];
    const float* ry_p  = (const float*)d_in[2];
    const float* ry2_p = (const float*)d_in[3];
    const float* crx_p = (const float*)d_in[4];
    const float* u3_p  = (const float*)d_in[5];
    const float* u3b_p = (const float*)d_in[6];
    const float* W1    = (const float*)d_in[7];
    const float* b1    = (const float*)d_in[8];
    const float* W2    = (const float*)d_in[9];
    const float* b2    = (const float*)d_in[10];

    int B = in_sizes[0] / 32;          // x is (B, 32)
    const int threads = 128;           // 4 warps/block, 8 elements/block
    int blocks = (B + 7) / 8;
    qcnn_kernel<<<blocks, threads>>>(x, rz_p, ry_p, ry2_p, crx_p, u3_p, u3b_p,
                                     W1, b1, W2, b2, (float*)d_out, B);
}